// round 8
// baseline (speedup 1.0000x reference)
#include <cuda_runtime.h>
#include <cuda_bf16.h>
#include <cuda_fp16.h>
#include <cstdint>

#define N_NODES 100000
#define N_EDGES 1600000
#define EMB 64
#define HID 128
#define N_GRAPHS 512
#define N_TASKS 128
#define FULLMASK 0xffffffffu

// ---------------- device scratch (static, no allocation) ----------------
__device__ __align__(16) uint4 g_x0h[N_NODES * 8];     // 64 halves per node
__device__ __align__(16) uint4 g_agg0h[N_NODES * 8];
__device__ __align__(16) uint4 g_x1h[N_NODES * 16];    // 128 halves per node
__device__ __align__(16) uint4 g_agg1h[N_NODES * 16];
__device__ __align__(16) uint4 g_t0h[16 * 8];          // bond table L0 (fp16)
__device__ __align__(16) uint4 g_t1h[16 * 16];         // bond table L1 (fp16)
__device__ __align__(16) float g_pool[N_GRAPHS * HID];
// fp16 weights, pre-swizzled to match smem layout exactly:
// layer0: [W1 16384 | W2 32768]   layer1: [W1 32768 | W2 32768]
__device__ __align__(16) unsigned char g_wb0[49152];
__device__ __align__(16) unsigned char g_wb1[65536];

// ---------------- helpers ----------------
__device__ __forceinline__ void red_add_v2(float* p, float a, float b) {
    asm volatile("red.global.add.v2.f32 [%0], {%1,%2};"
                 :: "l"(p), "f"(a), "f"(b) : "memory");
}
__device__ __forceinline__ void red_add_f(float* p, float v) {
    asm volatile("red.global.add.f32 [%0], %1;" :: "l"(p), "f"(v) : "memory");
}
__device__ __forceinline__ void red_add_f16x8(uint4* p, uint4 v) {
    asm volatile("red.global.add.noftz.v4.f16x2 [%0], {%1,%2,%3,%4};"
                 :: "l"(p), "r"(v.x), "r"(v.y), "r"(v.z), "r"(v.w) : "memory");
}
__device__ __forceinline__ void cp16(uint32_t dst, const void* src, bool valid) {
    if (valid)
        asm volatile("cp.async.cg.shared.global [%0], [%1], 16;" :: "r"(dst), "l"(src) : "memory");
    else
        asm volatile("cp.async.cg.shared.global [%0], [%1], 16, 0;" :: "r"(dst), "l"(src) : "memory");
}
__device__ __forceinline__ float elu_fast(float x) { return x > 0.f ? x : (__expf(x) - 1.f); }
__device__ __forceinline__ uint32_t smem_u32(const void* p) {
    uint32_t a;
    asm("{ .reg .u64 t; cvta.to.shared.u64 t, %1; cvt.u32.u64 %0, t; }" : "=r"(a) : "l"(p));
    return a;
}
// half2 relu(a+b)
__device__ __forceinline__ uint32_t h2ra(uint32_t a, uint32_t b) {
    __half2 s = __hadd2(*(__half2*)&a, *(__half2*)&b);
    __half2 z = __float2half2_rn(0.f);
    s = __hmax2(s, z);
    return *(uint32_t*)&s;
}
__device__ __forceinline__ uint4 msg4(uint4 v, uint4 t) {
    uint4 m;
    m.x = h2ra(v.x, t.x); m.y = h2ra(v.y, t.y);
    m.z = h2ra(v.z, t.z); m.w = h2ra(v.w, t.w);
    return m;
}
__device__ __forceinline__ uint32_t packh2(float a, float b) {
    __half2 h = __floats2half2_rn(a, b);
    return *(uint32_t*)&h;
}
// swizzled byte offset within a [row][col] 16-bit-element tile; rowb bytes per row.
__device__ __forceinline__ uint32_t swz(int r, int c, int rowb) {
    return (uint32_t)(r * rowb + ((((c >> 3) ^ (r & 7))) << 4) + (c & 7) * 2);
}
__device__ __forceinline__ void ldsm_x4(uint32_t a[4], uint32_t addr) {
    asm volatile("ldmatrix.sync.aligned.m8n8.x4.shared.b16 {%0,%1,%2,%3}, [%4];"
                 : "=r"(a[0]), "=r"(a[1]), "=r"(a[2]), "=r"(a[3]) : "r"(addr));
}
__device__ __forceinline__ void ldsm_x4_t(uint32_t a[4], uint32_t addr) {
    asm volatile("ldmatrix.sync.aligned.m8n8.x4.trans.shared.b16 {%0,%1,%2,%3}, [%4];"
                 : "=r"(a[0]), "=r"(a[1]), "=r"(a[2]), "=r"(a[3]) : "r"(addr));
}
__device__ __forceinline__ void mma_fp16(float d[4], const uint32_t a[4], uint32_t b0, uint32_t b1) {
    asm volatile("mma.sync.aligned.m16n8k16.row.col.f32.f16.f16.f32 "
                 "{%0,%1,%2,%3}, {%4,%5,%6,%7}, {%8,%9}, {%0,%1,%2,%3};"
                 : "+f"(d[0]), "+f"(d[1]), "+f"(d[2]), "+f"(d[3])
                 : "r"(a[0]), "r"(a[1]), "r"(a[2]), "r"(a[3]), "r"(b0), "r"(b1));
}

// ---------------- prep: pool zero + fp16 bond tables + fp16 weight blobs + gather ----------------
__global__ void k_prep(const float* __restrict__ bond_emb,
                       const float* __restrict__ we0, const float* __restrict__ be0,
                       const float* __restrict__ we1, const float* __restrict__ be1,
                       const float* __restrict__ w1_0, const float* __restrict__ w2_0,
                       const float* __restrict__ w1_1, const float* __restrict__ w2_1,
                       const int* __restrict__ x_idx, const float* __restrict__ atom_emb) {
    int tid = blockIdx.x * blockDim.x + threadIdx.x;
    int nth = gridDim.x * blockDim.x;
    for (int i = tid; i < N_GRAPHS * HID; i += nth) g_pool[i] = 0.f;
    for (int i = tid; i < 16 * EMB; i += nth) {
        int bt = i >> 6, o = i & 63;
        float acc = be0[o];
        #pragma unroll 8
        for (int k = 0; k < EMB; k++) acc += bond_emb[bt * EMB + k] * we0[k * EMB + o];
        ((__half*)g_t0h)[i] = __float2half_rn(acc);
    }
    for (int i = tid; i < 16 * HID; i += nth) {
        int bt = i >> 7, o = i & 127;
        float acc = be1[o];
        #pragma unroll 8
        for (int k = 0; k < EMB; k++) acc += bond_emb[bt * EMB + k] * we1[k * HID + o];
        ((__half*)g_t1h)[i] = __float2half_rn(acc);
    }
    for (int i = tid; i < 64 * 128; i += nth) {          // L0 W1
        int k = i >> 7, n = i & 127;
        *(__half*)(g_wb0 + swz(k, n, 256)) = __float2half_rn(w1_0[i]);
    }
    for (int i = tid; i < 128 * 128; i += nth) {         // L0 W2
        int k = i >> 7, n = i & 127;
        *(__half*)(g_wb0 + 16384 + swz(k, n, 256)) = __float2half_rn(w2_0[i]);
    }
    for (int i = tid; i < 128 * 128; i += nth) {         // L1 W1
        int k = i >> 7, n = i & 127;
        *(__half*)(g_wb1 + swz(k, n, 256)) = __float2half_rn(w1_1[i]);
    }
    for (int i = tid; i < 128 * 128; i += nth) {         // L1 W2
        int k = i >> 7, n = i & 127;
        *(__half*)(g_wb1 + 32768 + swz(k, n, 256)) = __float2half_rn(w2_1[i]);
    }
    // gather atom embeddings (fp32 -> fp16) + zero agg0
    const float4* ae = (const float4*)atom_emb;
    uint2* x0 = (uint2*)g_x0h;
    uint2* a0 = (uint2*)g_agg0h;
    const int NITEMS = N_NODES * 16;
    for (int i = tid; i < NITEMS; i += nth) {
        int node = i >> 4;
        int c = i & 15;
        int a = x_idx[node];
        float4 v = ae[a * 16 + c];
        uint2 o;
        o.x = packh2(v.x, v.y); o.y = packh2(v.z, v.w);
        x0[i] = o;
        a0[i] = make_uint2(0u, 0u);
    }
}

// ---------------- edge layer 0: fp16, 4 edges per warp step ----------------
__global__ void k_edge0(const int* __restrict__ ei, const int* __restrict__ ea) {
    __shared__ uint4 t0s[16 * 8];
    for (int i = threadIdx.x; i < 16 * 8; i += blockDim.x) t0s[i] = g_t0h[i];
    __syncthreads();
    int lane = threadIdx.x & 31;
    int wid = (blockIdx.x * blockDim.x + threadIdx.x) >> 5;
    int nw = (gridDim.x * blockDim.x) >> 5;
    int e = lane >> 3, c = lane & 7;
    const int NB = N_EDGES / 32;
    for (int b = wid; b < NB; b += nw) {
        int base = b * 32;
        int s_l = ei[base + lane];
        int d_l = ei[N_EDGES + base + lane];
        int t_l = ea[base + lane];
        #pragma unroll 4
        for (int j = 0; j < 8; j++) {
            int idx = 4 * j + e;
            int src = __shfl_sync(FULLMASK, s_l, idx);
            int dst = __shfl_sync(FULLMASK, d_l, idx);
            int bt  = __shfl_sync(FULLMASK, t_l, idx);
            uint4 v = g_x0h[src * 8 + c];
            uint4 t = t0s[bt * 8 + c];
            red_add_f16x8(&g_agg0h[dst * 8 + c], msg4(v, t));
        }
    }
}

// ---------------- edge layer 1: fp16, 2 edges per warp step ----------------
__global__ void k_edge1(const int* __restrict__ ei, const int* __restrict__ ea) {
    __shared__ uint4 t1s[16 * 16];
    for (int i = threadIdx.x; i < 16 * 16; i += blockDim.x) t1s[i] = g_t1h[i];
    __syncthreads();
    int lane = threadIdx.x & 31;
    int wid = (blockIdx.x * blockDim.x + threadIdx.x) >> 5;
    int nw = (gridDim.x * blockDim.x) >> 5;
    int e = lane >> 4, c = lane & 15;
    const int NB = N_EDGES / 32;
    for (int b = wid; b < NB; b += nw) {
        int base = b * 32;
        int s_l = ei[base + lane];
        int d_l = ei[N_EDGES + base + lane];
        int t_l = ea[base + lane];
        #pragma unroll 4
        for (int j = 0; j < 16; j++) {
            int idx = 2 * j + e;
            int src = __shfl_sync(FULLMASK, s_l, idx);
            int dst = __shfl_sync(FULLMASK, d_l, idx);
            int bt  = __shfl_sync(FULLMASK, t_l, idx);
            uint4 v = g_x1h[src * 16 + c];
            uint4 t = t1s[bt * 16 + c];
            red_add_f16x8(&g_agg1h[dst * 16 + c], msg4(v, t));
        }
    }
}

// ============ GINE MLP: cp.async-pipelined HMMA fp16 ============
// GEMM1 uses linearity: (x+agg)@W1 = x@W1 + agg@W1 — x and agg tiles are
// cp.async'd raw (swizzled dst) with zero staging compute; B frags shared.
template<int K1, bool L1>
__global__ void __launch_bounds__(1024, 1)
k_mlp_cp(const float* __restrict__ b1, const float* __restrict__ b2,
         const int* __restrict__ batch) {
    extern __shared__ char smem[];
    constexpr int W1B = K1 * 256;
    constexpr int W2B = 32768;
    constexpr int RB  = K1 * 2;            // bytes per row of Xs/Gs
    constexpr int XSB = 128 * RB;
    constexpr int CPR = RB / 16;           // 16B chunks per row
    constexpr int NGS = 16;                // smem pool graphs (L1 only)
    char* W1s  = smem;
    char* W2s  = smem + W1B;
    char* Xsb  = smem + W1B + W2B;
    char* Gsb  = Xsb + XSB;
    char* As2b = Gsb + XSB;
    float* b1s = (float*)(As2b + 32768);
    float* b2s = b1s + 128;
    float* pool_s = b2s + 128;             // L1 only: NGS*128 floats

    const char* xg = (const char*)(L1 ? (const uint4*)g_x1h : (const uint4*)g_x0h);
    const char* ag = (const char*)(L1 ? (const uint4*)g_agg1h : (const uint4*)g_agg0h);
    const unsigned char* blob = L1 ? g_wb1 : g_wb0;

    int tid = threadIdx.x;
    {
        const uint4* src = (const uint4*)blob;
        uint4* dst = (uint4*)smem;
        for (int i = tid; i < (W1B + W2B) / 16; i += 1024) dst[i] = src[i];
    }
    if (tid < 128) { b1s[tid] = b1[tid]; b2s[tid] = b2[tid]; }
    if constexpr (L1) {
        for (int i = tid; i < NGS * 128; i += 1024) pool_s[i] = 0.f;
    }

    uint32_t Xs_u = smem_u32(Xsb), Gs_u = smem_u32(Gsb);
    uint32_t As2_u = smem_u32(As2b);
    uint32_t W1_u = smem_u32(W1s), W2_u = smem_u32(W2s);

    int lane = tid & 31, wq = tid >> 5;
    int mbase = (wq & 7) * 16;
    int nbase = (wq >> 3) * 32;
    int g = lane >> 3, lr = lane & 7;
    int fr = (g & 1) * 8 + lr;
    int fc8 = (g >> 1) * 8;
    int qr = lane >> 2, qp = lane & 3;

    const int NT = (N_NODES + 127) / 128;  // 782

    auto prefetch = [&](int T) {
        #pragma unroll
        for (int v = 0; v < (2 * 128 * CPR) / 1024; v++) {
            int idx = v * 1024 + tid;
            int which = idx / (128 * CPR);
            int rem = idx % (128 * CPR);
            int r = rem / CPR, c = rem % CPR;
            int node = T * 128 + r;
            uint32_t dst = (which ? Gs_u : Xs_u) + r * RB + (uint32_t)((c ^ (r & 7)) << 4);
            const char* sb = which ? ag : xg;
            bool valid = node < N_NODES;
            const char* src = valid ? sb + ((size_t)node * RB + c * 16) : sb;
            cp16(dst, src, valid);
        }
        asm volatile("cp.async.commit_group;" ::: "memory");
    };

    if ((int)blockIdx.x < NT) prefetch(blockIdx.x);
    __syncthreads();   // weights/bias/pool visible (cp.async waits handled per tile)

    for (int tile = blockIdx.x; tile < NT; tile += gridDim.x) {
        asm volatile("cp.async.wait_group 0;" ::: "memory");
        __syncthreads();

        float d0[4][4] = {};

        // ---- GEMM1: x@W1 + agg@W1 ----
        #pragma unroll
        for (int ks = 0; ks < K1 / 16; ks++) {
            uint32_t aX[4], aG[4];
            ldsm_x4(aX, Xs_u + swz(mbase + fr, ks * 16 + fc8, RB));
            ldsm_x4(aG, Gs_u + swz(mbase + fr, ks * 16 + fc8, RB));
            #pragma unroll
            for (int np = 0; np < 2; np++) {
                uint32_t bh[4];
                ldsm_x4_t(bh, W1_u + swz(ks * 16 + fr, nbase + np * 16 + fc8, 256));
                mma_fp16(d0[2 * np],     aX, bh[0], bh[1]);
                mma_fp16(d0[2 * np + 1], aX, bh[2], bh[3]);
                mma_fp16(d0[2 * np],     aG, bh[0], bh[1]);
                mma_fp16(d0[2 * np + 1], aG, bh[2], bh[3]);
            }
        }

        // ---- epilogue1: t = elu(D + b1) -> As2 (fp16, swizzled) ----
        #pragma unroll
        for (int i = 0; i < 4; i++) {
            int n = nbase + i * 8 + qp * 2;
            float bb0 = b1s[n], bb1 = b1s[n + 1];
            *(uint32_t*)(As2b + swz(mbase + qr,     n, 256)) = packh2(elu_fast(d0[i][0] + bb0), elu_fast(d0[i][1] + bb1));
            *(uint32_t*)(As2b + swz(mbase + qr + 8, n, 256)) = packh2(elu_fast(d0[i][2] + bb0), elu_fast(d0[i][3] + bb1));
        }
        __syncthreads();   // As2 ready; Xs/Gs free (all GEMM1 reads done)

        // ---- prefetch next tile (overlaps GEMM2) ----
        int nxt = tile + gridDim.x;
        if (nxt < NT) prefetch(nxt);

        #pragma unroll
        for (int i = 0; i < 4; i++)
            #pragma unroll
            for (int j = 0; j < 4; j++) d0[i][j] = 0.f;

        // ---- GEMM2: t[128x128] @ W2 ----
        #pragma unroll
        for (int ks = 0; ks < 8; ks++) {
            uint32_t a0[4];
            ldsm_x4(a0, As2_u + swz(mbase + fr, ks * 16 + fc8, 256));
            #pragma unroll
            for (int np = 0; np < 2; np++) {
                uint32_t bh[4];
                ldsm_x4_t(bh, W2_u + swz(ks * 16 + fr, nbase + np * 16 + fc8, 256));
                mma_fp16(d0[2 * np],     a0, bh[0], bh[1]);
                mma_fp16(d0[2 * np + 1], a0, bh[2], bh[3]);
            }
        }

        // ---- epilogue2 ----
        if constexpr (!L1) {
            #pragma unroll
            for (int f = 0; f < 2; f++) {
                int row = mbase + qr + f * 8;
                int node = tile * 128 + row;
                if (node < N_NODES) {
                    uint32_t* xo = (uint32_t*)g_x1h + (size_t)node * 64;
                    uint32_t* ao = (uint32_t*)g_agg1h + (size_t)node * 64;
                    #pragma unroll
                    for (int i = 0; i < 4; i++) {
                        int n = nbase + i * 8 + qp * 2;
                        float o0 = elu_fast(d0[i][2 * f]     + b2s[n]);
                        float o1 = elu_fast(d0[i][2 * f + 1] + b2s[n + 1]);
                        xo[n >> 1] = packh2(o0, o1);
                        ao[n >> 1] = 0u;
                    }
                }
            }
            // loop-top sync of next iteration orders GEMM2 reads vs next epi1 writes
        } else {
            int gbase = batch[tile * 128];
            #pragma unroll
            for (int f = 0; f < 2; f++) {
                int row = mbase + qr + f * 8;
                int node = tile * 128 + row;
                if (node < N_NODES) {
                    int gl = batch[node] - gbase;
                    #pragma unroll
                    for (int i = 0; i < 4; i++) {
                        int n = nbase + i * 8 + qp * 2;
                        float o0 = elu_fast(d0[i][2 * f]     + b2s[n]);
                        float o1 = elu_fast(d0[i][2 * f + 1] + b2s[n + 1]);
                        if (gl < NGS) {
                            atomicAdd(&pool_s[gl * 128 + n], o0);
                            atomicAdd(&pool_s[gl * 128 + n + 1], o1);
                        } else {
                            red_add_v2(g_pool + (size_t)(gbase + gl) * HID + n, o0, o1);
                        }
                    }
                }
            }
            __syncthreads();   // all pool_s atomics done
            // flush + re-zero smem pool (partial sums are additive across tiles)
            for (int i = tid; i < NGS * 128; i += 1024) {
                float v = pool_s[i];
                if (v != 0.f) {
                    pool_s[i] = 0.f;
                    red_add_f(g_pool + (size_t)(gbase + (i >> 7)) * HID + (i & 127), v);
                }
            }
        }
        __syncthreads();   // protect As2 / pool_s across iterations
    }
}

// ---------------- head ----------------
__global__ void k_head(const float* __restrict__ w1, const float* __restrict__ b1,
                       const float* __restrict__ w2, const float* __restrict__ b2,
                       float* __restrict__ out) {
    __shared__ float p_s[HID], h_s[HID];
    int g = blockIdx.x, t = threadIdx.x;
    p_s[t] = g_pool[g * HID + t];
    __syncthreads();
    float acc = b1[t];
    #pragma unroll 8
    for (int k = 0; k < HID; k++) acc += p_s[k] * w1[k * N_TASKS + t];
    h_s[t] = fmaxf(acc, 0.f);
    __syncthreads();
    acc = b2[t];
    #pragma unroll 8
    for (int k = 0; k < HID; k++) acc += h_s[k] * w2[k * N_TASKS + t];
    out[g * N_TASKS + t] = acc;
}

// ---------------- launch ----------------
extern "C" void kernel_launch(void* const* d_in, const int* in_sizes, int n_in,
                              void* d_out, int out_size) {
    const int*   x_idx    = (const int*)  d_in[0];
    const int*   ei       = (const int*)  d_in[1];
    const int*   ea       = (const int*)  d_in[2];
    const int*   batch    = (const int*)  d_in[3];
    const float* atom_emb = (const float*)d_in[4];
    const float* bond_emb = (const float*)d_in[5];
    const float* we0      = (const float*)d_in[6];
    const float* be0      = (const float*)d_in[7];
    const float* w1_0     = (const float*)d_in[8];
    const float* b1_0     = (const float*)d_in[9];
    const float* w2_0     = (const float*)d_in[10];
    const float* b2_0     = (const float*)d_in[11];
    const float* we1      = (const float*)d_in[12];
    const float* be1      = (const float*)d_in[13];
    const float* w1_1     = (const float*)d_in[14];
    const float* b1_1     = (const float*)d_in[15];
    const float* w2_1     = (const float*)d_in[16];
    const float* b2_1     = (const float*)d_in[17];
    const float* lin1_w   = (const float*)d_in[18];
    const float* lin1_b   = (const float*)d_in[19];
    const float* lin2_w   = (const float*)d_in[20];
    const float* lin2_b   = (const float*)d_in[21];
    float* out = (float*)d_out;

    // smem: W1 + W2 + Xs + Gs + As2 + biases (+ pool for L1)
    int smem0 = 16384 + 32768 + 16384 + 16384 + 32768 + 1024;          // 115712
    int smem1 = 32768 + 32768 + 32768 + 32768 + 32768 + 1024 + 8192;   // 171008
    cudaFuncSetAttribute(k_mlp_cp<64, false>, cudaFuncAttributeMaxDynamicSharedMemorySize, smem0);
    cudaFuncSetAttribute(k_mlp_cp<128, true>, cudaFuncAttributeMaxDynamicSharedMemorySize, smem1);

    k_prep  <<<2048, 256>>>(bond_emb, we0, be0, we1, be1, w1_0, w2_0, w1_1, w2_1, x_idx, atom_emb);
    k_edge0 <<<1480, 256>>>(ei, ea);
    k_mlp_cp<64, false><<<148, 1024, smem0>>>(b1_0, b2_0, batch);
    k_edge1 <<<1480, 256>>>(ei, ea);
    k_mlp_cp<128, true><<<148, 1024, smem1>>>(b1_1, b2_1, batch);
    k_head  <<<512, 128>>>(lin1_w, lin1_b, lin2_w, lin2_b, out);
}

// round 9
// speedup vs baseline: 1.1384x; 1.1384x over previous
#include <cuda_runtime.h>
#include <cuda_bf16.h>
#include <cuda_fp16.h>
#include <cstdint>

#define N_NODES 100000
#define N_EDGES 1600000
#define EMB 64
#define HID 128
#define N_GRAPHS 512
#define N_TASKS 128
#define FULLMASK 0xffffffffu
#define NB_SCAN 98   // ceil(100000/1024)

// ---------------- device scratch (static, no allocation) ----------------
__device__ __align__(16) uint4 g_x0h[N_NODES * 8];     // 64 halves per node
__device__ __align__(16) uint4 g_agg0h[N_NODES * 8];
__device__ __align__(16) uint4 g_x1h[N_NODES * 16];    // 128 halves per node
__device__ __align__(16) uint4 g_agg1h[N_NODES * 16];
__device__ __align__(16) uint4 g_t0h[16 * 8];          // bond table L0 (fp16)
__device__ __align__(16) uint4 g_t1h[16 * 16];         // bond table L1 (fp16)
__device__ __align__(16) float g_pool[N_GRAPHS * HID];
// fp16 weights, pre-swizzled: layer0 [W1 16384 | W2 32768], layer1 [W1 32768 | W2 32768]
__device__ __align__(16) unsigned char g_wb0[49152];
__device__ __align__(16) unsigned char g_wb1[65536];
// CSR (built once per launch, shared by both layers)
__device__ int g_deg[N_NODES];
__device__ int g_off[N_NODES + 1];
__device__ int g_cur[N_NODES];
__device__ int g_bsum[NB_SCAN];
__device__ uint32_t g_csr[N_EDGES];    // src | (bt << 17)

// ---------------- helpers ----------------
__device__ __forceinline__ void red_add_v2(float* p, float a, float b) {
    asm volatile("red.global.add.v2.f32 [%0], {%1,%2};"
                 :: "l"(p), "f"(a), "f"(b) : "memory");
}
__device__ __forceinline__ float elu_fast(float x) { return x > 0.f ? x : (__expf(x) - 1.f); }
__device__ __forceinline__ uint32_t smem_u32(const void* p) {
    uint32_t a;
    asm("{ .reg .u64 t; cvta.to.shared.u64 t, %1; cvt.u32.u64 %0, t; }" : "=r"(a) : "l"(p));
    return a;
}
// half2 relu(a+b)
__device__ __forceinline__ uint32_t h2ra(uint32_t a, uint32_t b) {
    __half2 s = __hadd2(*(__half2*)&a, *(__half2*)&b);
    __half2 z = __float2half2_rn(0.f);
    s = __hmax2(s, z);
    return *(uint32_t*)&s;
}
__device__ __forceinline__ uint32_t h2a(uint32_t a, uint32_t b) {
    __half2 s = __hadd2(*(__half2*)&a, *(__half2*)&b);
    return *(uint32_t*)&s;
}
__device__ __forceinline__ uint4 hadd2x4(uint4 a, uint4 b) {
    uint4 o;
    o.x = h2a(a.x, b.x); o.y = h2a(a.y, b.y);
    o.z = h2a(a.z, b.z); o.w = h2a(a.w, b.w);
    return o;
}
__device__ __forceinline__ uint32_t packh2(float a, float b) {
    __half2 h = __floats2half2_rn(a, b);
    return *(uint32_t*)&h;
}
// swizzled byte offset within a [row][col] 16-bit-element tile; rowb bytes per row.
__device__ __forceinline__ uint32_t swz(int r, int c, int rowb) {
    return (uint32_t)(r * rowb + ((((c >> 3) ^ (r & 7))) << 4) + (c & 7) * 2);
}
__device__ __forceinline__ void ldsm_x4(uint32_t a[4], uint32_t addr) {
    asm volatile("ldmatrix.sync.aligned.m8n8.x4.shared.b16 {%0,%1,%2,%3}, [%4];"
                 : "=r"(a[0]), "=r"(a[1]), "=r"(a[2]), "=r"(a[3]) : "r"(addr));
}
__device__ __forceinline__ void ldsm_x4_t(uint32_t a[4], uint32_t addr) {
    asm volatile("ldmatrix.sync.aligned.m8n8.x4.trans.shared.b16 {%0,%1,%2,%3}, [%4];"
                 : "=r"(a[0]), "=r"(a[1]), "=r"(a[2]), "=r"(a[3]) : "r"(addr));
}
__device__ __forceinline__ void mma_fp16(float d[4], const uint32_t a[4], uint32_t b0, uint32_t b1) {
    asm volatile("mma.sync.aligned.m16n8k16.row.col.f32.f16.f16.f32 "
                 "{%0,%1,%2,%3}, {%4,%5,%6,%7}, {%8,%9}, {%0,%1,%2,%3};"
                 : "+f"(d[0]), "+f"(d[1]), "+f"(d[2]), "+f"(d[3])
                 : "r"(a[0]), "r"(a[1]), "r"(a[2]), "r"(a[3]), "r"(b0), "r"(b1));
}

// ---------------- init: pool zero + deg zero + fp16 bond tables + fp16 weight blobs ----
__global__ void k_init(const float* __restrict__ bond_emb,
                       const float* __restrict__ we0, const float* __restrict__ be0,
                       const float* __restrict__ we1, const float* __restrict__ be1,
                       const float* __restrict__ w1_0, const float* __restrict__ w2_0,
                       const float* __restrict__ w1_1, const float* __restrict__ w2_1) {
    int tid = blockIdx.x * blockDim.x + threadIdx.x;
    int nth = gridDim.x * blockDim.x;
    for (int i = tid; i < N_GRAPHS * HID; i += nth) g_pool[i] = 0.f;
    for (int i = tid; i < N_NODES; i += nth) g_deg[i] = 0;
    for (int i = tid; i < 16 * EMB; i += nth) {
        int bt = i >> 6, o = i & 63;
        float acc = be0[o];
        #pragma unroll 8
        for (int k = 0; k < EMB; k++) acc += bond_emb[bt * EMB + k] * we0[k * EMB + o];
        ((__half*)g_t0h)[i] = __float2half_rn(acc);
    }
    for (int i = tid; i < 16 * HID; i += nth) {
        int bt = i >> 7, o = i & 127;
        float acc = be1[o];
        #pragma unroll 8
        for (int k = 0; k < EMB; k++) acc += bond_emb[bt * EMB + k] * we1[k * HID + o];
        ((__half*)g_t1h)[i] = __float2half_rn(acc);
    }
    for (int i = tid; i < 64 * 128; i += nth) {
        int k = i >> 7, n = i & 127;
        *(__half*)(g_wb0 + swz(k, n, 256)) = __float2half_rn(w1_0[i]);
    }
    for (int i = tid; i < 128 * 128; i += nth) {
        int k = i >> 7, n = i & 127;
        *(__half*)(g_wb0 + 16384 + swz(k, n, 256)) = __float2half_rn(w2_0[i]);
    }
    for (int i = tid; i < 128 * 128; i += nth) {
        int k = i >> 7, n = i & 127;
        *(__half*)(g_wb1 + swz(k, n, 256)) = __float2half_rn(w1_1[i]);
    }
    for (int i = tid; i < 128 * 128; i += nth) {
        int k = i >> 7, n = i & 127;
        *(__half*)(g_wb1 + 32768 + swz(k, n, 256)) = __float2half_rn(w2_1[i]);
    }
}

// ---------------- gather atom embeddings (fp32 -> fp16) ----------------
__global__ void k_gather(const int* __restrict__ x_idx, const float* __restrict__ atom_emb) {
    int tid = blockIdx.x * blockDim.x + threadIdx.x;
    int nth = gridDim.x * blockDim.x;
    const float4* ae = (const float4*)atom_emb;
    uint2* x0 = (uint2*)g_x0h;
    const int NITEMS = N_NODES * 16;
    for (int i = tid; i < NITEMS; i += nth) {
        int node = i >> 4;
        int c = i & 15;
        int a = x_idx[node];
        float4 v = ae[a * 16 + c];
        uint2 o;
        o.x = packh2(v.x, v.y); o.y = packh2(v.z, v.w);
        x0[i] = o;
    }
}

// ---------------- CSR build ----------------
__global__ void k_hist(const int* __restrict__ ei) {
    int tid = blockIdx.x * blockDim.x + threadIdx.x;
    int nth = gridDim.x * blockDim.x;
    for (int e = tid; e < N_EDGES; e += nth)
        atomicAdd(&g_deg[ei[N_EDGES + e]], 1);
}

__global__ void k_scan1() {
    __shared__ int s[1024];
    int i = blockIdx.x * 1024 + threadIdx.x;
    int v = (i < N_NODES) ? g_deg[i] : 0;
    s[threadIdx.x] = v;
    __syncthreads();
    #pragma unroll
    for (int d = 1; d < 1024; d <<= 1) {
        int t = (threadIdx.x >= d) ? s[threadIdx.x - d] : 0;
        __syncthreads();
        s[threadIdx.x] += t;
        __syncthreads();
    }
    if (i < N_NODES) g_off[i] = s[threadIdx.x] - v;   // exclusive
    if (threadIdx.x == 1023) g_bsum[blockIdx.x] = s[1023];
}

__global__ void k_scan2() {
    __shared__ int bs[NB_SCAN];
    if (threadIdx.x < NB_SCAN) bs[threadIdx.x] = g_bsum[threadIdx.x];
    __syncthreads();
    int add = 0;
    for (int b = 0; b < (int)blockIdx.x; b++) add += bs[b];
    int i = blockIdx.x * 1024 + threadIdx.x;
    if (i < N_NODES) {
        int o = g_off[i] + add;
        g_off[i] = o;
        g_cur[i] = o;
    }
    if (blockIdx.x == NB_SCAN - 1 && threadIdx.x == 0)
        g_off[N_NODES] = add + bs[NB_SCAN - 1];
}

__global__ void k_scatter(const int* __restrict__ ei, const int* __restrict__ ea) {
    int tid = blockIdx.x * blockDim.x + threadIdx.x;
    int nth = gridDim.x * blockDim.x;
    for (int e = tid; e < N_EDGES; e += nth) {
        int d = ei[N_EDGES + e];
        uint32_t rec = (uint32_t)ei[e] | ((uint32_t)ea[e] << 17);
        int pos = atomicAdd(&g_cur[d], 1);
        g_csr[pos] = rec;
    }
}

// ---------------- CSR aggregation layer 0: half-warp per node, 8B chunks ----
__global__ void k_agg0() {
    __shared__ uint2 t0s[16 * 16];
    for (int i = threadIdx.x; i < 16 * 16; i += blockDim.x) t0s[i] = ((const uint2*)g_t0h)[i];
    __syncthreads();
    int lane = threadIdx.x & 31;
    int wid = (blockIdx.x * blockDim.x + threadIdx.x) >> 5;
    int nw = (gridDim.x * blockDim.x) >> 5;
    int e = lane >> 4, c = lane & 15;
    const uint2* x0 = (const uint2*)g_x0h;
    uint2* a0 = (uint2*)g_agg0h;
    const int NP = N_NODES / 2;   // 50000, exact
    for (int p = wid; p < NP; p += nw) {
        int n = 2 * p + e;
        int beg = g_off[n];
        int len = g_off[n + 1] - beg;
        int ml = __reduce_max_sync(FULLMASK, len);
        uint32_t a_x = 0u, a_y = 0u;   // half2 accumulators (zeros)
        for (int k = 0; k < ml; k++) {
            bool act = k < len;
            if (act) {
                uint32_t rec = g_csr[beg + k];
                int src = rec & 0x1FFFF;
                int bt  = rec >> 17;
                uint2 v = x0[src * 16 + c];
                uint2 t = t0s[bt * 16 + c];
                a_x = h2a(a_x, h2ra(v.x, t.x));
                a_y = h2a(a_y, h2ra(v.y, t.y));
            }
        }
        uint2 o; o.x = a_x; o.y = a_y;
        a0[n * 16 + c] = o;
    }
}

// ---------------- CSR aggregation layer 1: half-warp per node, 16B chunks ----
__global__ void k_agg1() {
    __shared__ uint4 t1s[16 * 16];
    for (int i = threadIdx.x; i < 16 * 16; i += blockDim.x) t1s[i] = g_t1h[i];
    __syncthreads();
    int lane = threadIdx.x & 31;
    int wid = (blockIdx.x * blockDim.x + threadIdx.x) >> 5;
    int nw = (gridDim.x * blockDim.x) >> 5;
    int e = lane >> 4, c = lane & 15;
    const int NP = N_NODES / 2;
    for (int p = wid; p < NP; p += nw) {
        int n = 2 * p + e;
        int beg = g_off[n];
        int len = g_off[n + 1] - beg;
        int ml = __reduce_max_sync(FULLMASK, len);
        uint4 acc = make_uint4(0u, 0u, 0u, 0u);
        for (int k = 0; k < ml; k++) {
            bool act = k < len;
            if (act) {
                uint32_t rec = g_csr[beg + k];
                int src = rec & 0x1FFFF;
                int bt  = rec >> 17;
                uint4 v = g_x1h[src * 16 + c];
                uint4 t = t1s[bt * 16 + c];
                acc.x = h2a(acc.x, h2ra(v.x, t.x));
                acc.y = h2a(acc.y, h2ra(v.y, t.y));
                acc.z = h2a(acc.z, h2ra(v.z, t.z));
                acc.w = h2a(acc.w, h2ra(v.w, t.w));
            }
        }
        g_agg1h[n * 16 + c] = acc;
    }
}

// ============ GINE MLP on HMMA fp16 (R7): 1024 threads, 32 warps, m16 x n32 per warp ============
template<int K1, bool L1>
__global__ void __launch_bounds__(1024, 1)
k_mlp_mma(const float* __restrict__ b1, const float* __restrict__ b2,
          const int* __restrict__ batch) {
    extern __shared__ char smem[];
    constexpr int W1B = K1 * 256;
    constexpr int W2B = 128 * 256;
    constexpr int RB1 = K1 * 2;
    constexpr int ASB = 128 * RB1;
    constexpr int AS2B = 128 * 256;
    constexpr int BLOB = W1B + W2B;
    char* W1s  = smem;
    char* W2s  = smem + W1B;
    char* Asb  = smem + BLOB;
    char* As2b = Asb + ASB;
    float* b1s = (float*)(As2b + AS2B);
    float* b2s = b1s + 128;

    const uint4* xh = L1 ? g_x1h : g_x0h;
    const uint4* ah = L1 ? g_agg1h : g_agg0h;
    const unsigned char* blob = L1 ? g_wb1 : g_wb0;

    int tid = threadIdx.x;
    {
        const uint4* src = (const uint4*)blob;
        uint4* dst = (uint4*)smem;
        for (int i = tid; i < BLOB / 16; i += 1024) dst[i] = src[i];
    }
    if (tid < 128) { b1s[tid] = b1[tid]; b2s[tid] = b2[tid]; }

    uint32_t As_u  = smem_u32(Asb);
    uint32_t As2_u = smem_u32(As2b);
    uint32_t W1_u  = smem_u32(W1s);
    uint32_t W2_u  = smem_u32(W2s);

    int lane = tid & 31, wq = tid >> 5;
    int mbase = (wq & 7) * 16;
    int nbase = (wq >> 3) * 32;
    int g = lane >> 3, lr = lane & 7;
    int fr = (g & 1) * 8 + lr;
    int fc8 = (g >> 1) * 8;
    int qr = lane >> 2, qp = lane & 3;

    const int NT = (N_NODES + 127) / 128;    // 782
    __syncthreads();

    for (int tile = blockIdx.x; tile < NT; tile += gridDim.x) {
        // ---- stage As: fp16 (x + agg), swizzled; 8 threads/row ----
        {
            int r = tid >> 3;
            int q = tid & 7;
            int node = tile * 128 + r;
            char* rowp = Asb + r * RB1;
            constexpr int CH = K1 / 64;
            if (node < N_NODES) {
                const uint4* xp = xh + (size_t)node * (K1 / 8) + q * CH;
                const uint4* ap = ah + (size_t)node * (K1 / 8) + q * CH;
                #pragma unroll
                for (int c = 0; c < CH; c++) {
                    int kk = (q * CH + c) * 8;
                    uint4 pk = hadd2x4(xp[c], ap[c]);
                    *(uint4*)(rowp + ((((kk >> 3) ^ (r & 7))) << 4)) = pk;
                }
            } else {
                uint4 z = make_uint4(0u, 0u, 0u, 0u);
                #pragma unroll
                for (int c = 0; c < CH; c++) {
                    int kk = (q * CH + c) * 8;
                    *(uint4*)(rowp + ((((kk >> 3) ^ (r & 7))) << 4)) = z;
                }
            }
        }
        __syncthreads();

        float d0[4][4];
        #pragma unroll
        for (int i = 0; i < 4; i++)
            #pragma unroll
            for (int j = 0; j < 4; j++) d0[i][j] = 0.f;

        // ---- GEMM1: A[128xK1] @ W1 ----
        #pragma unroll
        for (int ks = 0; ks < K1 / 16; ks++) {
            uint32_t a0[4];
            ldsm_x4(a0, As_u + swz(mbase + fr, ks * 16 + fc8, RB1));
            #pragma unroll
            for (int np = 0; np < 2; np++) {
                uint32_t bh[4];
                ldsm_x4_t(bh, W1_u + swz(ks * 16 + fr, nbase + np * 16 + fc8, 256));
                mma_fp16(d0[2 * np], a0, bh[0], bh[1]);
                mma_fp16(d0[2 * np + 1], a0, bh[2], bh[3]);
            }
        }

        // ---- epilogue1: t = elu(D + b1) -> As2 (fp16, swizzled) ----
        #pragma unroll
        for (int i = 0; i < 4; i++) {
            int n = nbase + i * 8 + qp * 2;
            float bb0 = b1s[n], bb1 = b1s[n + 1];
            *(uint32_t*)(As2b + swz(mbase + qr,     n, 256)) = packh2(elu_fast(d0[i][0] + bb0), elu_fast(d0[i][1] + bb1));
            *(uint32_t*)(As2b + swz(mbase + qr + 8, n, 256)) = packh2(elu_fast(d0[i][2] + bb0), elu_fast(d0[i][3] + bb1));
        }
        __syncthreads();

        #pragma unroll
        for (int i = 0; i < 4; i++)
            #pragma unroll
            for (int j = 0; j < 4; j++) d0[i][j] = 0.f;

        // ---- GEMM2: t[128x128] @ W2 ----
        #pragma unroll
        for (int ks = 0; ks < 8; ks++) {
            uint32_t a0[4];
            ldsm_x4(a0, As2_u + swz(mbase + fr, ks * 16 + fc8, 256));
            #pragma unroll
            for (int np = 0; np < 2; np++) {
                uint32_t bh[4];
                ldsm_x4_t(bh, W2_u + swz(ks * 16 + fr, nbase + np * 16 + fc8, 256));
                mma_fp16(d0[2 * np], a0, bh[0], bh[1]);
                mma_fp16(d0[2 * np + 1], a0, bh[2], bh[3]);
            }
        }

        // ---- epilogue2 ----
        if constexpr (!L1) {
            #pragma unroll
            for (int f = 0; f < 2; f++) {
                int row = mbase + qr + f * 8;
                int node = tile * 128 + row;
                if (node < N_NODES) {
                    uint32_t* xo = (uint32_t*)g_x1h + (size_t)node * 64;
                    #pragma unroll
                    for (int i = 0; i < 4; i++) {
                        int n = nbase + i * 8 + qp * 2;
                        float o0 = elu_fast(d0[i][2 * f]     + b2s[n]);
                        float o1 = elu_fast(d0[i][2 * f + 1] + b2s[n + 1]);
                        xo[n >> 1] = packh2(o0, o1);
                    }
                }
            }
        } else {
            #pragma unroll
            for (int f = 0; f < 2; f++) {
                int row = mbase + qr + f * 8;
                int node = tile * 128 + row;
                if (node < N_NODES) {
                    int gg = batch[node];
                    float* pp = g_pool + (size_t)gg * HID;
                    #pragma unroll
                    for (int i = 0; i < 4; i++) {
                        int n = nbase + i * 8 + qp * 2;
                        float o0 = elu_fast(d0[i][2 * f]     + b2s[n]);
                        float o1 = elu_fast(d0[i][2 * f + 1] + b2s[n + 1]);
                        red_add_v2(pp + n, o0, o1);
                    }
                }
            }
        }
        __syncthreads();
    }
}

// ---------------- head ----------------
__global__ void k_head(const float* __restrict__ w1, const float* __restrict__ b1,
                       const float* __restrict__ w2, const float* __restrict__ b2,
                       float* __restrict__ out) {
    __shared__ float p_s[HID], h_s[HID];
    int g = blockIdx.x, t = threadIdx.x;
    p_s[t] = g_pool[g * HID + t];
    __syncthreads();
    float acc = b1[t];
    #pragma unroll 8
    for (int k = 0; k < HID; k++) acc += p_s[k] * w1[k * N_TASKS + t];
    h_s[t] = fmaxf(acc, 0.f);
    __syncthreads();
    acc = b2[t];
    #pragma unroll 8
    for (int k = 0; k < HID; k++) acc += h_s[k] * w2[k * N_TASKS + t];
    out[g * N_TASKS + t] = acc;
}

// ---------------- launch ----------------
extern "C" void kernel_launch(void* const* d_in, const int* in_sizes, int n_in,
                              void* d_out, int out_size) {
    const int*   x_idx    = (const int*)  d_in[0];
    const int*   ei       = (const int*)  d_in[1];
    const int*   ea       = (const int*)  d_in[2];
    const int*   batch    = (const int*)  d_in[3];
    const float* atom_emb = (const float*)d_in[4];
    const float* bond_emb = (const float*)d_in[5];
    const float* we0      = (const float*)d_in[6];
    const float* be0      = (const float*)d_in[7];
    const float* w1_0     = (const float*)d_in[8];
    const float* b1_0     = (const float*)d_in[9];
    const float* w2_0     = (const float*)d_in[10];
    const float* b2_0     = (const float*)d_in[11];
    const float* we1      = (const float*)d_in[12];
    const float* be1      = (const float*)d_in[13];
    const float* w1_1     = (const float*)d_in[14];
    const float* b1_1     = (const float*)d_in[15];
    const float* w2_1     = (const float*)d_in[16];
    const float* b2_1     = (const float*)d_in[17];
    const float* lin1_w   = (const float*)d_in[18];
    const float* lin1_b   = (const float*)d_in[19];
    const float* lin2_w   = (const float*)d_in[20];
    const float* lin2_b   = (const float*)d_in[21];
    float* out = (float*)d_out;

    int smem0 = 16384 + 32768 + 16384 + 32768 + 1024;   //  99328
    int smem1 = 32768 + 32768 + 32768 + 32768 + 1024;   // 132096
    cudaFuncSetAttribute(k_mlp_mma<64, false>, cudaFuncAttributeMaxDynamicSharedMemorySize, smem0);
    cudaFuncSetAttribute(k_mlp_mma<128, true>, cudaFuncAttributeMaxDynamicSharedMemorySize, smem1);

    k_init   <<<128, 256>>>(bond_emb, we0, be0, we1, be1, w1_0, w2_0, w1_1, w2_1);
    k_gather <<<2048, 256>>>(x_idx, atom_emb);
    k_hist   <<<1480, 256>>>(ei);
    k_scan1  <<<NB_SCAN, 1024>>>();
    k_scan2  <<<NB_SCAN, 1024>>>();
    k_scatter<<<1480, 256>>>(ei, ea);
    k_agg0   <<<1480, 256>>>();
    k_mlp_mma<64, false><<<148, 1024, smem0>>>(b1_0, b2_0, batch);
    k_agg1   <<<1480, 256>>>();
    k_mlp_mma<128, true><<<148, 1024, smem1>>>(b1_1, b2_1, batch);
    k_head   <<<512, 128>>>(lin1_w, lin1_b, lin2_w, lin2_b, out);
}

// round 11
// speedup vs baseline: 1.3245x; 1.1635x over previous
#include <cuda_runtime.h>
#include <cuda_bf16.h>
#include <cuda_fp16.h>
#include <cstdint>

#define N_NODES 100000
#define N_EDGES 1600000
#define EMB 64
#define HID 128
#define N_GRAPHS 512
#define N_TASKS 128
#define FULLMASK 0xffffffffu

// ---------------- device scratch (static, no allocation) ----------------
__device__ __align__(16) uint4 g_x0h[N_NODES * 8];     // 64 halves per node
__device__ __align__(16) uint4 g_agg0h[N_NODES * 8];   // init = x0; edges add msgs
__device__ __align__(16) uint4 g_x1h[N_NODES * 16];    // 128 halves per node
__device__ __align__(16) uint4 g_agg1h[N_NODES * 16];  // init = x1; edges add msgs
__device__ __align__(16) uint4 g_t0h[16 * 8];          // bond table L0 (fp16)
__device__ __align__(16) uint4 g_t1h[16 * 16];         // bond table L1 (fp16)
__device__ __align__(16) float g_pool[N_GRAPHS * HID];
// fp16 weights, pre-swizzled: layer0 [W1 16384 | W2 32768], layer1 [W1 32768 | W2 32768]
__device__ __align__(16) unsigned char g_wb0[49152];
__device__ __align__(16) unsigned char g_wb1[65536];

// ---------------- helpers ----------------
__device__ __forceinline__ void red_add_v2(float* p, float a, float b) {
    asm volatile("red.global.add.v2.f32 [%0], {%1,%2};"
                 :: "l"(p), "f"(a), "f"(b) : "memory");
}
__device__ __forceinline__ void red_add_f16x8(uint4* p, uint4 v) {
    asm volatile("red.global.add.noftz.v4.f16x2 [%0], {%1,%2,%3,%4};"
                 :: "l"(p), "r"(v.x), "r"(v.y), "r"(v.z), "r"(v.w) : "memory");
}
__device__ __forceinline__ void cp16(uint32_t dst, const void* src, bool valid) {
    if (valid)
        asm volatile("cp.async.cg.shared.global [%0], [%1], 16;" :: "r"(dst), "l"(src) : "memory");
    else
        asm volatile("cp.async.cg.shared.global [%0], [%1], 16, 0;" :: "r"(dst), "l"(src) : "memory");
}
__device__ __forceinline__ float elu_fast(float x) { return x > 0.f ? x : (__expf(x) - 1.f); }
__device__ __forceinline__ uint32_t smem_u32(const void* p) {
    uint32_t a;
    asm("{ .reg .u64 t; cvta.to.shared.u64 t, %1; cvt.u32.u64 %0, t; }" : "=r"(a) : "l"(p));
    return a;
}
// half2 relu(a+b)
__device__ __forceinline__ uint32_t h2ra(uint32_t a, uint32_t b) {
    __half2 s = __hadd2(*(__half2*)&a, *(__half2*)&b);
    __half2 z = __float2half2_rn(0.f);
    s = __hmax2(s, z);
    return *(uint32_t*)&s;
}
__device__ __forceinline__ uint4 msg4(uint4 v, uint4 t) {
    uint4 m;
    m.x = h2ra(v.x, t.x); m.y = h2ra(v.y, t.y);
    m.z = h2ra(v.z, t.z); m.w = h2ra(v.w, t.w);
    return m;
}
__device__ __forceinline__ uint32_t packh2(float a, float b) {
    __half2 h = __floats2half2_rn(a, b);
    return *(uint32_t*)&h;
}
// swizzled byte offset within a [row][col] 16-bit-element tile; rowb bytes per row.
__device__ __forceinline__ uint32_t swz(int r, int c, int rowb) {
    return (uint32_t)(r * rowb + ((((c >> 3) ^ (r & 7))) << 4) + (c & 7) * 2);
}
__device__ __forceinline__ void ldsm_x4(uint32_t a[4], uint32_t addr) {
    asm volatile("ldmatrix.sync.aligned.m8n8.x4.shared.b16 {%0,%1,%2,%3}, [%4];"
                 : "=r"(a[0]), "=r"(a[1]), "=r"(a[2]), "=r"(a[3]) : "r"(addr));
}
__device__ __forceinline__ void ldsm_x4_t(uint32_t a[4], uint32_t addr) {
    asm volatile("ldmatrix.sync.aligned.m8n8.x4.trans.shared.b16 {%0,%1,%2,%3}, [%4];"
                 : "=r"(a[0]), "=r"(a[1]), "=r"(a[2]), "=r"(a[3]) : "r"(addr));
}
__device__ __forceinline__ void mma_fp16(float d[4], const uint32_t a[4], uint32_t b0, uint32_t b1) {
    asm volatile("mma.sync.aligned.m16n8k16.row.col.f32.f16.f16.f32 "
                 "{%0,%1,%2,%3}, {%4,%5,%6,%7}, {%8,%9}, {%0,%1,%2,%3};"
                 : "+f"(d[0]), "+f"(d[1]), "+f"(d[2]), "+f"(d[3])
                 : "r"(a[0]), "r"(a[1]), "r"(a[2]), "r"(a[3]), "r"(b0), "r"(b1));
}

// ---------------- prep: pool zero + fp16 bond tables + fp16 weight blobs + gather ----
// gather sets x0h AND agg0h = x0 (aggregator pre-biased with x).
__global__ void k_prep(const float* __restrict__ bond_emb,
                       const float* __restrict__ we0, const float* __restrict__ be0,
                       const float* __restrict__ we1, const float* __restrict__ be1,
                       const float* __restrict__ w1_0, const float* __restrict__ w2_0,
                       const float* __restrict__ w1_1, const float* __restrict__ w2_1,
                       const int* __restrict__ x_idx, const float* __restrict__ atom_emb) {
    int tid = blockIdx.x * blockDim.x + threadIdx.x;
    int nth = gridDim.x * blockDim.x;
    for (int i = tid; i < N_GRAPHS * HID; i += nth) g_pool[i] = 0.f;
    for (int i = tid; i < 16 * EMB; i += nth) {
        int bt = i >> 6, o = i & 63;
        float acc = be0[o];
        #pragma unroll 8
        for (int k = 0; k < EMB; k++) acc += bond_emb[bt * EMB + k] * we0[k * EMB + o];
        ((__half*)g_t0h)[i] = __float2half_rn(acc);
    }
    for (int i = tid; i < 16 * HID; i += nth) {
        int bt = i >> 7, o = i & 127;
        float acc = be1[o];
        #pragma unroll 8
        for (int k = 0; k < EMB; k++) acc += bond_emb[bt * EMB + k] * we1[k * HID + o];
        ((__half*)g_t1h)[i] = __float2half_rn(acc);
    }
    for (int i = tid; i < 64 * 128; i += nth) {          // L0 W1
        int k = i >> 7, n = i & 127;
        *(__half*)(g_wb0 + swz(k, n, 256)) = __float2half_rn(w1_0[i]);
    }
    for (int i = tid; i < 128 * 128; i += nth) {         // L0 W2
        int k = i >> 7, n = i & 127;
        *(__half*)(g_wb0 + 16384 + swz(k, n, 256)) = __float2half_rn(w2_0[i]);
    }
    for (int i = tid; i < 128 * 128; i += nth) {         // L1 W1
        int k = i >> 7, n = i & 127;
        *(__half*)(g_wb1 + swz(k, n, 256)) = __float2half_rn(w1_1[i]);
    }
    for (int i = tid; i < 128 * 128; i += nth) {         // L1 W2
        int k = i >> 7, n = i & 127;
        *(__half*)(g_wb1 + 32768 + swz(k, n, 256)) = __float2half_rn(w2_1[i]);
    }
    // gather atom embeddings (fp32 -> fp16); agg0 = x0
    const float4* ae = (const float4*)atom_emb;
    uint2* x0 = (uint2*)g_x0h;
    uint2* a0 = (uint2*)g_agg0h;
    const int NITEMS = N_NODES * 16;
    for (int i = tid; i < NITEMS; i += nth) {
        int node = i >> 4;
        int c = i & 15;
        int a = x_idx[node];
        float4 v = ae[a * 16 + c];
        uint2 o;
        o.x = packh2(v.x, v.y); o.y = packh2(v.z, v.w);
        x0[i] = o;
        a0[i] = o;
    }
}

// ---------------- edge layer 0: fp16, 4 edges per warp step ----------------
__global__ void k_edge0(const int* __restrict__ ei, const int* __restrict__ ea) {
    __shared__ uint4 t0s[16 * 8];
    for (int i = threadIdx.x; i < 16 * 8; i += blockDim.x) t0s[i] = g_t0h[i];
    __syncthreads();
    int lane = threadIdx.x & 31;
    int wid = (blockIdx.x * blockDim.x + threadIdx.x) >> 5;
    int nw = (gridDim.x * blockDim.x) >> 5;
    int e = lane >> 3, c = lane & 7;
    const int NB = N_EDGES / 32;
    for (int b = wid; b < NB; b += nw) {
        int base = b * 32;
        int s_l = ei[base + lane];
        int d_l = ei[N_EDGES + base + lane];
        int t_l = ea[base + lane];
        #pragma unroll 4
        for (int j = 0; j < 8; j++) {
            int idx = 4 * j + e;
            int src = __shfl_sync(FULLMASK, s_l, idx);
            int dst = __shfl_sync(FULLMASK, d_l, idx);
            int bt  = __shfl_sync(FULLMASK, t_l, idx);
            uint4 v = g_x0h[src * 8 + c];
            uint4 t = t0s[bt * 8 + c];
            red_add_f16x8(&g_agg0h[dst * 8 + c], msg4(v, t));
        }
    }
}

// ---------------- edge layer 1: fp16, 2 edges per warp step ----------------
__global__ void k_edge1(const int* __restrict__ ei, const int* __restrict__ ea) {
    __shared__ uint4 t1s[16 * 16];
    for (int i = threadIdx.x; i < 16 * 16; i += blockDim.x) t1s[i] = g_t1h[i];
    __syncthreads();
    int lane = threadIdx.x & 31;
    int wid = (blockIdx.x * blockDim.x + threadIdx.x) >> 5;
    int nw = (gridDim.x * blockDim.x) >> 5;
    int e = lane >> 4, c = lane & 15;
    const int NB = N_EDGES / 32;
    for (int b = wid; b < NB; b += nw) {
        int base = b * 32;
        int s_l = ei[base + lane];
        int d_l = ei[N_EDGES + base + lane];
        int t_l = ea[base + lane];
        #pragma unroll 4
        for (int j = 0; j < 16; j++) {
            int idx = 2 * j + e;
            int src = __shfl_sync(FULLMASK, s_l, idx);
            int dst = __shfl_sync(FULLMASK, d_l, idx);
            int bt  = __shfl_sync(FULLMASK, t_l, idx);
            uint4 v = g_x1h[src * 16 + c];
            uint4 t = t1s[bt * 16 + c];
            red_add_f16x8(&g_agg1h[dst * 16 + c], msg4(v, t));
        }
    }
}

// ============ GINE MLP: cp.async-pipelined HMMA fp16 ============
// agg already holds (x + Σmsg): staging is a raw cp.async copy, GEMM1 single-operand.
template<int K1, bool L1>
__global__ void __launch_bounds__(1024, 1)
k_mlp_cp(const float* __restrict__ b1, const float* __restrict__ b2,
         const int* __restrict__ batch) {
    extern __shared__ char smem[];
    constexpr int W1B = K1 * 256;
    constexpr int W2B = 32768;
    constexpr int RB  = K1 * 2;            // bytes per As row
    constexpr int ASB = 128 * RB;
    constexpr int CPR = RB / 16;           // 16B chunks per row (8 or 16)
    char* W1s  = smem;
    char* W2s  = smem + W1B;
    char* Asb  = smem + W1B + W2B;
    char* As2b = Asb + ASB;
    float* b1s = (float*)(As2b + 32768);
    float* b2s = b1s + 128;

    const char* ag = (const char*)(L1 ? g_agg1h : g_agg0h);
    const unsigned char* blob = L1 ? g_wb1 : g_wb0;

    int tid = threadIdx.x;
    {
        const uint4* src = (const uint4*)blob;
        uint4* dst = (uint4*)smem;
        for (int i = tid; i < (W1B + W2B) / 16; i += 1024) dst[i] = src[i];
    }
    if (tid < 128) { b1s[tid] = b1[tid]; b2s[tid] = b2[tid]; }

    uint32_t As_u  = smem_u32(Asb);
    uint32_t As2_u = smem_u32(As2b);
    uint32_t W1_u  = smem_u32(W1s);
    uint32_t W2_u  = smem_u32(W2s);

    int lane = tid & 31, wq = tid >> 5;
    int mbase = (wq & 7) * 16;
    int nbase = (wq >> 3) * 32;
    int g = lane >> 3, lr = lane & 7;
    int fr = (g & 1) * 8 + lr;
    int fc8 = (g >> 1) * 8;
    int qr = lane >> 2, qp = lane & 3;

    const int NT = (N_NODES + 127) / 128;  // 782

    auto prefetch = [&](int T) {
        #pragma unroll
        for (int v = 0; v < (128 * CPR) / 1024; v++) {
            int idx = v * 1024 + tid;
            int r = idx / CPR, c = idx % CPR;
            int node = T * 128 + r;
            uint32_t dst = As_u + r * RB + (uint32_t)((c ^ (r & 7)) << 4);
            bool valid = node < N_NODES;
            const char* src = valid ? ag + ((size_t)node * RB + c * 16) : ag;
            cp16(dst, src, valid);
        }
        asm volatile("cp.async.commit_group;" ::: "memory");
    };

    if ((int)blockIdx.x < NT) prefetch(blockIdx.x);

    for (int tile = blockIdx.x; tile < NT; tile += gridDim.x) {
        asm volatile("cp.async.wait_group 0;" ::: "memory");
        __syncthreads();   // As (and first-pass weights) visible to all

        float d0[4][4];
        #pragma unroll
        for (int i = 0; i < 4; i++)
            #pragma unroll
            for (int j = 0; j < 4; j++) d0[i][j] = 0.f;

        // ---- GEMM1: A[128xK1] @ W1 ----
        #pragma unroll
        for (int ks = 0; ks < K1 / 16; ks++) {
            uint32_t a0[4];
            ldsm_x4(a0, As_u + swz(mbase + fr, ks * 16 + fc8, RB));
            #pragma unroll
            for (int np = 0; np < 2; np++) {
                uint32_t bh[4];
                ldsm_x4_t(bh, W1_u + swz(ks * 16 + fr, nbase + np * 16 + fc8, 256));
                mma_fp16(d0[2 * np], a0, bh[0], bh[1]);
                mma_fp16(d0[2 * np + 1], a0, bh[2], bh[3]);
            }
        }

        // ---- epilogue1: t = elu(D + b1) -> As2 (fp16, swizzled) ----
        #pragma unroll
        for (int i = 0; i < 4; i++) {
            int n = nbase + i * 8 + qp * 2;
            float bb0 = b1s[n], bb1 = b1s[n + 1];
            *(uint32_t*)(As2b + swz(mbase + qr,     n, 256)) = packh2(elu_fast(d0[i][0] + bb0), elu_fast(d0[i][1] + bb1));
            *(uint32_t*)(As2b + swz(mbase + qr + 8, n, 256)) = packh2(elu_fast(d0[i][2] + bb0), elu_fast(d0[i][3] + bb1));
        }
        __syncthreads();   // As2 ready; all GEMM1 reads of As done

        // ---- prefetch next tile into As (overlaps GEMM2 + epilogue2) ----
        int nxt = tile + gridDim.x;
        if (nxt < NT) prefetch(nxt);

        #pragma unroll
        for (int i = 0; i < 4; i++)
            #pragma unroll
            for (int j = 0; j < 4; j++) d0[i][j] = 0.f;

        // ---- GEMM2: t[128x128] @ W2 ----
        #pragma unroll
        for (int ks = 0; ks < 8; ks++) {
            uint32_t a0[4];
            ldsm_x4(a0, As2_u + swz(mbase + fr, ks * 16 + fc8, 256));
            #pragma unroll
            for (int np = 0; np < 2; np++) {
                uint32_t bh[4];
                ldsm_x4_t(bh, W2_u + swz(ks * 16 + fr, nbase + np * 16 + fc8, 256));
                mma_fp16(d0[2 * np], a0, bh[0], bh[1]);
                mma_fp16(d0[2 * np + 1], a0, bh[2], bh[3]);
            }
        }

        // ---- epilogue2 ----
        if constexpr (!L1) {
            // x1 = out; agg1 = out (pre-biased aggregator for layer 1)
            #pragma unroll
            for (int f = 0; f < 2; f++) {
                int row = mbase + qr + f * 8;
                int node = tile * 128 + row;
                if (node < N_NODES) {
                    uint32_t* xo = (uint32_t*)g_x1h + (size_t)node * 64;
                    uint32_t* ao = (uint32_t*)g_agg1h + (size_t)node * 64;
                    #pragma unroll
                    for (int i = 0; i < 4; i++) {
                        int n = nbase + i * 8 + qp * 2;
                        float o0 = elu_fast(d0[i][2 * f]     + b2s[n]);
                        float o1 = elu_fast(d0[i][2 * f + 1] + b2s[n + 1]);
                        uint32_t pk = packh2(o0, o1);
                        xo[n >> 1] = pk;
                        ao[n >> 1] = pk;
                    }
                }
            }
        } else {
            #pragma unroll
            for (int f = 0; f < 2; f++) {
                int row = mbase + qr + f * 8;
                int node = tile * 128 + row;
                if (node < N_NODES) {
                    int gg = batch[node];
                    float* pp = g_pool + (size_t)gg * HID;
                    #pragma unroll
                    for (int i = 0; i < 4; i++) {
                        int n = nbase + i * 8 + qp * 2;
                        float o0 = elu_fast(d0[i][2 * f]     + b2s[n]);
                        float o1 = elu_fast(d0[i][2 * f + 1] + b2s[n + 1]);
                        red_add_v2(pp + n, o0, o1);
                    }
                }
            }
        }
        // loop-top wait_group + __syncthreads orders GEMM2 As2-reads vs next epi1 writes
    }
}

// ---------------- head ----------------
__global__ void k_head(const float* __restrict__ w1, const float* __restrict__ b1,
                       const float* __restrict__ w2, const float* __restrict__ b2,
                       float* __restrict__ out) {
    __shared__ float p_s[HID], h_s[HID];
    int g = blockIdx.x, t = threadIdx.x;
    p_s[t] = g_pool[g * HID + t];
    __syncthreads();
    float acc = b1[t];
    #pragma unroll 8
    for (int k = 0; k < HID; k++) acc += p_s[k] * w1[k * N_TASKS + t];
    h_s[t] = fmaxf(acc, 0.f);
    __syncthreads();
    acc = b2[t];
    #pragma unroll 8
    for (int k = 0; k < HID; k++) acc += h_s[k] * w2[k * N_TASKS + t];
    out[g * N_TASKS + t] = acc;
}

// ---------------- launch ----------------
extern "C" void kernel_launch(void* const* d_in, const int* in_sizes, int n_in,
                              void* d_out, int out_size) {
    const int*   x_idx    = (const int*)  d_in[0];
    const int*   ei       = (const int*)  d_in[1];
    const int*   ea       = (const int*)  d_in[2];
    const int*   batch    = (const int*)  d_in[3];
    const float* atom_emb = (const float*)d_in[4];
    const float* bond_emb = (const float*)d_in[5];
    const float* we0      = (const float*)d_in[6];
    const float* be0      = (const float*)d_in[7];
    const float* w1_0     = (const float*)d_in[8];
    const float* b1_0     = (const float*)d_in[9];
    const float* w2_0     = (const float*)d_in[10];
    const float* b2_0     = (const float*)d_in[11];
    const float* we1      = (const float*)d_in[12];
    const float* be1      = (const float*)d_in[13];
    const float* w1_1     = (const float*)d_in[14];
    const float* b1_1     = (const float*)d_in[15];
    const float* w2_1     = (const float*)d_in[16];
    const float* b2_1     = (const float*)d_in[17];
    const float* lin1_w   = (const float*)d_in[18];
    const float* lin1_b   = (const float*)d_in[19];
    const float* lin2_w   = (const float*)d_in[20];
    const float* lin2_b   = (const float*)d_in[21];
    float* out = (float*)d_out;

    // smem: W1 + W2 + As + As2 + biases
    int smem0 = 16384 + 32768 + 16384 + 32768 + 1024;   //  99328
    int smem1 = 32768 + 32768 + 32768 + 32768 + 1024;   // 132096
    cudaFuncSetAttribute(k_mlp_cp<64, false>, cudaFuncAttributeMaxDynamicSharedMemorySize, smem0);
    cudaFuncSetAttribute(k_mlp_cp<128, true>, cudaFuncAttributeMaxDynamicSharedMemorySize, smem1);

    k_prep  <<<2048, 256>>>(bond_emb, we0, be0, we1, be1, w1_0, w2_0, w1_1, w2_1, x_idx, atom_emb);
    k_edge0 <<<1480, 256>>>(ei, ea);
    k_mlp_cp<64, false><<<148, 1024, smem0>>>(b1_0, b2_0, batch);
    k_edge1 <<<1480, 256>>>(ei, ea);
    k_mlp_cp<128, true><<<148, 1024, smem1>>>(b1_1, b2_1, batch);
    k_head  <<<512, 128>>>(lin1_w, lin1_b, lin2_w, lin2_b, out);
}